// round 4
// baseline (speedup 1.0000x reference)
#include <cuda_runtime.h>
#include <cstdint>

#define Nn   2048
#define Ee   65536
#define INC  128
#define HIDc 32
#define LATc 16

// ---------------- scratch (no allocation allowed) ----------------
__device__ int   g_is64;
__device__ float g_deg [Nn];
__device__ float g_dinv[Nn];
__device__ float g_xw  [Nn*HIDc];
__device__ float g_agg1[Nn*HIDc];
__device__ float g_h1  [Nn*HIDc];
__device__ float g_hwmu[Nn*LATc];
__device__ float g_hwlv[Nn*LATc];
__device__ float g_aggmu[Nn*LATc];
__device__ float g_agglv[Nn*LATc];
__device__ float g_z  [Nn*LATc];
__device__ float g_hi [Nn*LATc];
__device__ float g_hj [Nn*LATc];

// Edge-index accessor: handles both int64 (as in reference) and int32
// (if the harness normalizes integer dtypes). g_is64 set by k_detect.
__device__ __forceinline__ int eidx(const void* p, int pos, int is64) {
    if (is64) return (int)((const long long*)p)[pos];
    return ((const int*)p)[pos];
}

// ---------------- kernels ----------------

// detect index dtype: node ids < 2048, so int64 storage => high 32 bits of
// every 8-byte word are zero. int32 storage => high words are random ids.
__global__ void k_detect(const void* ei) {
    if (threadIdx.x == 0 && blockIdx.x == 0) {
        const unsigned long long* p = (const unsigned long long*)ei;
        unsigned long long orv = 0;
#pragma unroll
        for (int k = 0; k < 64; k++) orv |= p[k];
        g_is64 = ((orv >> 32) == 0ull) ? 1 : 0;
    }
}

// reset accumulators; deg starts at 1.0 (self-loop)
__global__ void k_init() {
    int t = blockIdx.x * blockDim.x + threadIdx.x;   // 65536 threads
    if (t < Nn*HIDc) g_agg1[t] = 0.f;
    if (t < Nn*LATc) { g_aggmu[t] = 0.f; g_agglv[t] = 0.f; }
    if (t < Nn) g_deg[t] = 1.0f;
}

__global__ void k_deg(const void* __restrict__ ei) {
    int e = blockIdx.x * blockDim.x + threadIdx.x;
    int is64 = g_is64;
    if (e < Ee) atomicAdd(&g_deg[eidx(ei, Ee + e, is64)], 1.0f);
}

__global__ void k_dinv() {
    int i = blockIdx.x * blockDim.x + threadIdx.x;
    if (i < Nn) g_dinv[i] = rsqrtf(g_deg[i]);
}

// xw = x @ W1   (2048x128 @ 128x32), warp per row
__global__ void k_xw(const float* __restrict__ x, const float* __restrict__ W1) {
    __shared__ float xs[8][INC];
    int tid = threadIdx.y * 32 + threadIdx.x;
    for (int t = tid; t < 8 * INC; t += 256) {
        int r = t / INC, k = t % INC;
        xs[r][k] = x[(blockIdx.x * 8 + r) * INC + k];
    }
    __syncthreads();
    int row = blockIdx.x * 8 + threadIdx.y;
    int c   = threadIdx.x;
    float s = 0.f;
#pragma unroll 8
    for (int k = 0; k < INC; k++) s = fmaf(xs[threadIdx.y][k], W1[k * HIDc + c], s);
    g_xw[row * HIDc + c] = s;
}

// edge aggregation layer 1: warp per edge, lane per channel
__global__ void k_eagg1(const void* __restrict__ ei) {
    int w = (blockIdx.x * blockDim.x + threadIdx.x) >> 5;
    int c = threadIdx.x & 31;
    if (w >= Ee) return;
    int is64 = g_is64;
    int s = eidx(ei, w, is64), d = eidx(ei, Ee + w, is64);
    float nw = g_dinv[s] * g_dinv[d];
    atomicAdd(&g_agg1[d * HIDc + c], nw * g_xw[s * HIDc + c]);
}

// h1 = relu(agg + selfloop + b1)
__global__ void k_h1(const float* __restrict__ b1) {
    int t = blockIdx.x * 256 + threadIdx.x;          // Nn*HIDc threads
    int i = t >> 5, c = t & 31;
    float di = g_dinv[i];
    float v = g_agg1[t] + di * di * g_xw[t] + b1[c];
    g_h1[t] = fmaxf(v, 0.f);
}

// hwmu = h1 @ W_mu ; hwlv = h1 @ W_lv   (warp per row; lanes 0..15 mu, 16..31 lv)
__global__ void k_hw(const float* __restrict__ Wmu, const float* __restrict__ Wlv) {
    int row = blockIdx.x * 8 + threadIdx.y;
    int t = threadIdx.x;
    const float* W = (t < 16) ? Wmu : Wlv;
    int l = t & 15;
    float s = 0.f;
#pragma unroll
    for (int k = 0; k < HIDc; k++) s = fmaf(g_h1[row * HIDc + k], W[k * LATc + l], s);
    if (t < 16) g_hwmu[row * LATc + l] = s;
    else        g_hwlv[row * LATc + l] = s;
}

// edge aggregation layer 2 (mu + lv in one pass): warp per edge
__global__ void k_eagg2(const void* __restrict__ ei) {
    int w = (blockIdx.x * blockDim.x + threadIdx.x) >> 5;
    int t = threadIdx.x & 31;
    if (w >= Ee) return;
    int is64 = g_is64;
    int s = eidx(ei, w, is64), d = eidx(ei, Ee + w, is64);
    float nw = g_dinv[s] * g_dinv[d];
    int l = t & 15;
    if (t < 16) atomicAdd(&g_aggmu[d * LATc + l], nw * g_hwmu[s * LATc + l]);
    else        atomicAdd(&g_agglv[d * LATc + l], nw * g_hwlv[s * LATc + l]);
}

// finalize mu/logvar (write to d_out), reparameterize z
__global__ void k_z(const float* __restrict__ bmu, const float* __restrict__ blv,
                    const float* __restrict__ eps,
                    float* __restrict__ out_mu, float* __restrict__ out_lv) {
    int t = blockIdx.x * 256 + threadIdx.x;          // Nn*LATc threads
    int i = t >> 4, l = t & 15;
    float di = g_dinv[i]; float d2 = di * di;
    float mu = g_aggmu[t] + d2 * g_hwmu[t] + bmu[l];
    float lv = g_agglv[t] + d2 * g_hwlv[t] + blv[l];
    out_mu[t] = mu;
    out_lv[t] = lv;
    g_z[t] = fmaf(eps[t], __expf(0.5f * lv), mu);
}

// hi = z @ dW1[:L] + db1 (bias folded) ; hj = z @ dW1[L:]
__global__ void k_hij(const float* __restrict__ dW1, const float* __restrict__ db1) {
    int t = blockIdx.x * 256 + threadIdx.x;          // Nn*LATc threads
    int i = t >> 4, l = t & 15;
    float si = db1[l], sj = 0.f;
#pragma unroll
    for (int k = 0; k < LATc; k++) {
        float zk = g_z[i * LATc + k];
        si = fmaf(zk, dW1[k * LATc + l], si);
        sj = fmaf(zk, dW1[(LATc + k) * LATc + l], sj);
    }
    g_hi[t] = si;
    g_hj[t] = sj;
}

// zero adj_true with wide stores
__global__ void k_zero(float4* __restrict__ p) {
    int t = blockIdx.x * 256 + threadIdx.x;          // Nn*Nn/4 threads
    p[t] = make_float4(0.f, 0.f, 0.f, 0.f);
}

// scatter multiplicity into adj_true
__global__ void k_true(const void* __restrict__ eit, float* __restrict__ adj) {
    int e = blockIdx.x * 256 + threadIdx.x;
    int is64 = g_is64;
    if (e < Ee) atomicAdd(&adj[eidx(eit, e, is64) * Nn + eidx(eit, Ee + e, is64)], 1.0f);
}

// decoder: adj_pred[i][j] = sigmoid( sum_l relu(hi[i][l]+hj[j][l]) * w2[l] + b2 )
// block = 64x4 threads, tile = 4 rows x 256 cols; hj tile transposed in smem
__global__ void k_dec(const float* __restrict__ dW2, const float* __restrict__ db2,
                      float* __restrict__ adj) {
    __shared__ float hjs[LATc][257];
    __shared__ float w2[LATc];
    int tid = threadIdx.y * 64 + threadIdx.x;
    if (tid < LATc) w2[tid] = dW2[tid];
    int j0 = blockIdx.x * 256;
    for (int t = tid; t < 256 * LATc; t += 256) {
        int j = t >> 4, l = t & 15;
        hjs[l][j] = g_hj[(j0 + j) * LATc + l];       // coalesced LDG
    }
    __syncthreads();
    int i = blockIdx.y * 4 + threadIdx.y;
    float hi[LATc];
#pragma unroll
    for (int l = 0; l < LATc; l++) hi[l] = g_hi[i * LATc + l];
    float b2 = db2[0];
#pragma unroll
    for (int u = 0; u < 4; u++) {
        int j = threadIdx.x + u * 64;                // conflict-free LDS, coalesced STG
        float s = b2;
#pragma unroll
        for (int l = 0; l < LATc; l++)
            s = fmaf(fmaxf(hi[l] + hjs[l][j], 0.f), w2[l], s);
        adj[(size_t)i * Nn + j0 + j] = __fdividef(1.f, 1.f + __expf(-s));
    }
}

// ---------------- launcher ----------------
extern "C" void kernel_launch(void* const* d_in, const int* in_sizes, int n_in,
                              void* d_out, int out_size) {
    const float* x    = (const float*)d_in[0];
    const float* eps  = (const float*)d_in[1];
    const float* W1   = (const float*)d_in[2];
    const float* b1   = (const float*)d_in[3];
    const float* Wmu  = (const float*)d_in[4];
    const float* bmu  = (const float*)d_in[5];
    const float* Wlv  = (const float*)d_in[6];
    const float* blv  = (const float*)d_in[7];
    const float* dW1  = (const float*)d_in[8];
    const float* db1  = (const float*)d_in[9];
    const float* dW2  = (const float*)d_in[10];
    const float* db2  = (const float*)d_in[11];
    const void*  ei   = d_in[12];
    const void*  eit  = d_in[13];

    float* out      = (float*)d_out;
    float* adj_pred = out;
    float* adj_true = out + (size_t)Nn * Nn;
    float* out_mu   = out + 2 * (size_t)Nn * Nn;
    float* out_lv   = out_mu + Nn * LATc;

    k_detect<<<1, 32>>>(ei);
    k_init <<<256, 256>>>();
    k_deg  <<<Ee / 256, 256>>>(ei);
    k_dinv <<<Nn / 256, 256>>>();
    k_xw   <<<Nn / 8, dim3(32, 8)>>>(x, W1);
    k_eagg1<<<(Ee * 32) / 256, 256>>>(ei);
    k_h1   <<<(Nn * HIDc) / 256, 256>>>(b1);
    k_hw   <<<Nn / 8, dim3(32, 8)>>>(Wmu, Wlv);
    k_eagg2<<<(Ee * 32) / 256, 256>>>(ei);
    k_z    <<<(Nn * LATc) / 256, 256>>>(bmu, blv, eps, out_mu, out_lv);
    k_hij  <<<(Nn * LATc) / 256, 256>>>(dW1, db1);
    k_zero <<<(Nn * Nn / 4) / 256, 256>>>((float4*)adj_true);
    k_true <<<Ee / 256, 256>>>(eit, adj_true);
    k_dec  <<<dim3(Nn / 256, Nn / 4), dim3(64, 4)>>>(dW2, db2, adj_pred);
}

// round 6
// speedup vs baseline: 1.7921x; 1.7921x over previous
#include <cuda_runtime.h>
#include <cstdint>

#define Nn   2048
#define Ee   65536
#define INC  128
#define HIDc 32
#define LATc 16

// ---------------- scratch (no allocation allowed) ----------------
__device__ int   g_is64;
__device__ __align__(16) float g_deg  [Nn];
__device__ __align__(16) float g_dinv [Nn];
__device__ __align__(16) float g_xw   [Nn*HIDc];
__device__ __align__(16) float g_agg1 [Nn*HIDc];
__device__ __align__(16) float g_hwmu [Nn*LATc];
__device__ __align__(16) float g_hwlv [Nn*LATc];
__device__ __align__(16) float g_aggmu[Nn*LATc];
__device__ __align__(16) float g_agglv[Nn*LATc];
__device__ __align__(16) float g_hi   [Nn*LATc];
__device__ __align__(16) float g_hjT  [LATc*Nn];   // transposed: [l][i]

// ---------------- helpers ----------------
__device__ __forceinline__ int eidx(const void* p, int pos, int is64) {
    if (is64) return (int)((const long long*)p)[pos];
    return ((const int*)p)[pos];
}

__device__ __forceinline__ void red4(float* addr, float4 v) {
    asm volatile("red.global.add.v4.f32 [%0], {%1, %2, %3, %4};"
                 :: "l"(__cvta_generic_to_global(addr)),
                    "f"(v.x), "f"(v.y), "f"(v.z), "f"(v.w) : "memory");
}

__device__ __forceinline__ unsigned long long f32x2_add(unsigned long long a, unsigned long long b) {
    unsigned long long r;
    asm("add.rn.f32x2 %0, %1, %2;" : "=l"(r) : "l"(a), "l"(b)); return r;
}
__device__ __forceinline__ unsigned long long f32x2_fma(unsigned long long a, unsigned long long b, unsigned long long c) {
    unsigned long long r;
    asm("fma.rn.f32x2 %0, %1, %2, %3;" : "=l"(r) : "l"(a), "l"(b), "l"(c)); return r;
}
__device__ __forceinline__ unsigned long long pack2(float lo, float hi) {
    unsigned long long r;
    asm("mov.b64 %0, {%1, %2};" : "=l"(r) : "f"(lo), "f"(hi)); return r;
}
__device__ __forceinline__ float2 unpack2(unsigned long long v) {
    float2 f;
    asm("mov.b64 {%0, %1}, %2;" : "=f"(f.x), "=f"(f.y) : "l"(v)); return f;
}
__device__ __forceinline__ unsigned long long relu2(unsigned long long v) {
    float2 f = unpack2(v);
    return pack2(fmaxf(f.x, 0.f), fmaxf(f.y, 0.f));
}

// ---------------- kernels ----------------

// detect index dtype + reset accumulators; deg starts at 1.0 (self-loop)
__global__ void k_init(const void* ei) {
    int t = blockIdx.x * 256 + threadIdx.x;          // 65536 threads
    if (t == 0) {
        const unsigned long long* p = (const unsigned long long*)ei;
        unsigned long long orv = 0;
#pragma unroll
        for (int k = 0; k < 64; k++) orv |= p[k];
        g_is64 = ((orv >> 32) == 0ull) ? 1 : 0;
    }
    if (t < Nn*HIDc) g_agg1[t] = 0.f;
    if (t < Nn*LATc) { g_aggmu[t] = 0.f; g_agglv[t] = 0.f; }
    if (t < Nn) g_deg[t] = 1.0f;
}

__global__ void k_deg(const void* __restrict__ ei) {
    int e = blockIdx.x * 256 + threadIdx.x;
    int is64 = g_is64;
    if (e < Ee) atomicAdd(&g_deg[eidx(ei, Ee + e, is64)], 1.0f);
}

// xw = x @ W1 (2048x128 @ 128x32), warp per row; blocks 0..7 also compute dinv
__global__ void k_xw_dinv(const float* __restrict__ x, const float* __restrict__ W1) {
    __shared__ float xs[8][INC];
    int tid = threadIdx.y * 32 + threadIdx.x;
    if (blockIdx.x < 8) {
        int i = blockIdx.x * 256 + tid;
        g_dinv[i] = rsqrtf(g_deg[i]);
    }
    for (int t = tid; t < 8 * INC; t += 256) {
        int r = t / INC, k = t % INC;
        xs[r][k] = x[(blockIdx.x * 8 + r) * INC + k];
    }
    __syncthreads();
    int row = blockIdx.x * 8 + threadIdx.y;
    int c   = threadIdx.x;
    float s = 0.f;
#pragma unroll 8
    for (int k = 0; k < INC; k++) s = fmaf(xs[threadIdx.y][k], W1[k * HIDc + c], s);
    g_xw[row * HIDc + c] = s;
}

// edge aggregation layer 1: 4 threads/edge, each does 2 float4 chunks via red.v4
__global__ void k_eagg1(const void* __restrict__ ei) {
    int t = blockIdx.x * 256 + threadIdx.x;          // Ee*4 threads
    int e = t >> 2, c = t & 3;
    int is64 = g_is64;
    int s = eidx(ei, e, is64), d = eidx(ei, Ee + e, is64);
    float nw = g_dinv[s] * g_dinv[d];
    const float4* xw4 = (const float4*)g_xw;
    float4 a = xw4[s * 8 + c];
    float4 b = xw4[s * 8 + c + 4];
    a.x *= nw; a.y *= nw; a.z *= nw; a.w *= nw;
    b.x *= nw; b.y *= nw; b.z *= nw; b.w *= nw;
    red4(&g_agg1[d * HIDc + c * 4], a);
    red4(&g_agg1[d * HIDc + (c + 4) * 4], b);
}

// h1 = relu(agg + selfloop + b1) fused with hw = h1 @ {W_mu, W_lv} (shfl matvec)
__global__ void k_h1hw(const float* __restrict__ b1,
                       const float* __restrict__ Wmu, const float* __restrict__ Wlv) {
    int row  = blockIdx.x * 8 + (threadIdx.x >> 5);
    int lane = threadIdx.x & 31;
    float di = g_dinv[row];
    float h = fmaxf(g_agg1[row * HIDc + lane] + di * di * g_xw[row * HIDc + lane] + b1[lane], 0.f);
    const float* W = (lane < 16) ? Wmu : Wlv;
    int l = lane & 15;
    float s = 0.f;
#pragma unroll
    for (int k = 0; k < HIDc; k++) {
        float hk = __shfl_sync(0xffffffffu, h, k);
        s = fmaf(hk, W[k * LATc + l], s);
    }
    if (lane < 16) g_hwmu[row * LATc + l] = s;
    else           g_hwlv[row * LATc + l] = s;
}

// edge aggregation layer 2: 4 threads/edge (mu chunk + lv chunk each) via red.v4
__global__ void k_eagg2(const void* __restrict__ ei) {
    int t = blockIdx.x * 256 + threadIdx.x;          // Ee*4 threads
    int e = t >> 2, c = t & 3;
    int is64 = g_is64;
    int s = eidx(ei, e, is64), d = eidx(ei, Ee + e, is64);
    float nw = g_dinv[s] * g_dinv[d];
    const float4* mu4 = (const float4*)g_hwmu;
    const float4* lv4 = (const float4*)g_hwlv;
    float4 a = mu4[s * 4 + c];
    float4 b = lv4[s * 4 + c];
    a.x *= nw; a.y *= nw; a.z *= nw; a.w *= nw;
    b.x *= nw; b.y *= nw; b.z *= nw; b.w *= nw;
    red4(&g_aggmu[d * LATc + c * 4], a);
    red4(&g_agglv[d * LATc + c * 4], b);
}

// finalize mu/logvar, reparameterize z (regs only), and hi/hjT via shfl-16 matvec
__global__ void k_zhij(const float* __restrict__ bmu, const float* __restrict__ blv,
                       const float* __restrict__ eps,
                       const float* __restrict__ dW1, const float* __restrict__ db1,
                       float* __restrict__ out_mu, float* __restrict__ out_lv) {
    int t = blockIdx.x * 256 + threadIdx.x;          // Nn*LATc threads
    int i = t >> 4, l = t & 15;
    float di = g_dinv[i]; float d2 = di * di;
    float mu = g_aggmu[t] + d2 * g_hwmu[t] + bmu[l];
    float lv = g_agglv[t] + d2 * g_hwlv[t] + blv[l];
    out_mu[t] = mu;
    out_lv[t] = lv;
    float z = fmaf(eps[t], __expf(0.5f * lv), mu);
    float si = db1[l], sj = 0.f;
#pragma unroll
    for (int k = 0; k < LATc; k++) {
        float zk = __shfl_sync(0xffffffffu, z, k, 16);
        si = fmaf(zk, dW1[k * LATc + l], si);
        sj = fmaf(zk, dW1[(LATc + k) * LATc + l], sj);
    }
    g_hi[t] = si;
    g_hjT[l * Nn + i] = sj;                          // transposed for k_dec
}

// decoder + adj_true zeroing. block = 128 thr, tile = 8 rows x 256 cols.
// thread owns a packed j-pair; hj pair + w2 in regs, hi broadcast from smem.
__global__ void __launch_bounds__(128) k_dec(const float* __restrict__ dW2,
                                             const float* __restrict__ db2,
                                             float* __restrict__ adj,
                                             float* __restrict__ adjt) {
    __shared__ float his[8][16];
    int tx = threadIdx.x;
    int j0 = blockIdx.x * 256;
    int i0 = blockIdx.y * 8;

    // zero the matching adj_true tile (8 x 256 floats) with float4 stores
#pragma unroll
    for (int k = 0; k < 4; k++) {
        int idx = tx + k * 128;                      // 512 float4s
        ((float4*)(adjt + (size_t)(i0 + (idx >> 6)) * Nn + j0))[idx & 63] =
            make_float4(0.f, 0.f, 0.f, 0.f);
    }

    his[tx >> 4][tx & 15] = g_hi[(i0 + (tx >> 4)) * LATc + (tx & 15)];

    unsigned long long w2p[LATc], pj[LATc];
    float b2 = db2[0];
#pragma unroll
    for (int l = 0; l < LATc; l++) {
        float w = dW2[l];
        w2p[l] = pack2(w, w);
        float2 h = *(const float2*)&g_hjT[l * Nn + j0 + 2 * tx];
        pj[l] = pack2(h.x, h.y);
    }
    __syncthreads();

    size_t obase = (size_t)i0 * Nn + j0 + 2 * tx;
#pragma unroll
    for (int r = 0; r < 8; r++) {
        unsigned long long acc = pack2(b2, b2);
#pragma unroll
        for (int l = 0; l < LATc; l++) {
            float h = his[r][l];
            unsigned long long h2 = pack2(h, h);
            acc = f32x2_fma(relu2(f32x2_add(pj[l], h2)), w2p[l], acc);
        }
        float2 s = unpack2(acc);
        float2 o;
        o.x = __fdividef(1.f, 1.f + __expf(-s.x));
        o.y = __fdividef(1.f, 1.f + __expf(-s.y));
        *(float2*)&adj[obase + (size_t)r * Nn] = o;
    }
}

// scatter multiplicity into adj_true (after k_dec zeroed it)
__global__ void k_true(const void* __restrict__ eit, float* __restrict__ adj) {
    int e = blockIdx.x * 256 + threadIdx.x;
    int is64 = g_is64;
    if (e < Ee) atomicAdd(&adj[eidx(eit, e, is64) * Nn + eidx(eit, Ee + e, is64)], 1.0f);
}

// ---------------- launcher ----------------
extern "C" void kernel_launch(void* const* d_in, const int* in_sizes, int n_in,
                              void* d_out, int out_size) {
    const float* x    = (const float*)d_in[0];
    const float* eps  = (const float*)d_in[1];
    const float* W1   = (const float*)d_in[2];
    const float* b1   = (const float*)d_in[3];
    const float* Wmu  = (const float*)d_in[4];
    const float* bmu  = (const float*)d_in[5];
    const float* Wlv  = (const float*)d_in[6];
    const float* blv  = (const float*)d_in[7];
    const float* dW1  = (const float*)d_in[8];
    const float* db1  = (const float*)d_in[9];
    const float* dW2  = (const float*)d_in[10];
    const float* db2  = (const float*)d_in[11];
    const void*  ei   = d_in[12];
    const void*  eit  = d_in[13];

    float* out      = (float*)d_out;
    float* adj_pred = out;
    float* adj_true = out + (size_t)Nn * Nn;
    float* out_mu   = out + 2 * (size_t)Nn * Nn;
    float* out_lv   = out_mu + Nn * LATc;

    k_init   <<<256, 256>>>(ei);
    k_deg    <<<Ee / 256, 256>>>(ei);
    k_xw_dinv<<<Nn / 8, dim3(32, 8)>>>(x, W1);
    k_eagg1  <<<(Ee * 4) / 256, 256>>>(ei);
    k_h1hw   <<<Nn / 8, 256>>>(b1, Wmu, Wlv);
    k_eagg2  <<<(Ee * 4) / 256, 256>>>(ei);
    k_zhij   <<<(Nn * LATc) / 256, 256>>>(bmu, blv, eps, dW1, db1, out_mu, out_lv);
    k_dec    <<<dim3(Nn / 256, Nn / 8), 128>>>(dW2, db2, adj_pred, adj_true);
    k_true   <<<Ee / 256, 256>>>(eit, adj_true);
}